// round 1
// baseline (speedup 1.0000x reference)
#include <cuda_runtime.h>
#include <cuda_bf16.h>
#include <cstdint>

// TrainableActivation: per-channel RBF expansion
//   out[b,c,h,w] = sum_j w[c,j] * exp(-(x - mu_j)^2 / (2 sigma^2))
//   mu_j = linspace(-1, 1, 63), sigma = 2/62
//
// Transform: t = (x+1)*31, j = j0 + k (j0 = nearest knot),  u = t - j0
//   exp(-(u-k)^2/2) = exp(-u^2/2) * exp(u)^k * exp(-k^2/2)
// -> 3 MUFU per element, +/-6 tap window (truncation < 3e-7 rel).
// Weights replicated 32x lane-strided in shared: bank-conflict-free gather.

#define NW      63
#define PAD     6
#define SLOTS   (NW + 2 * PAD)      // 75
#define SIGMA   (2.0f / 62.0f)
#define INVS    31.0f

__global__ void __launch_bounds__(256, 6)
rbf_act_kernel(const float* __restrict__ x,
               const float* __restrict__ w,
               float* __restrict__ out)
{
    __shared__ float wsh[SLOTS * 32];   // wsh[j*32 + lane], j in [-6, 68] padded

    // 9 blocks per (batch, channel) slab of 9216 elements
    const int chan = (blockIdx.x / 9) & 63;
    const float* wrow = w + chan * NW;

    for (int i = threadIdx.x; i < SLOTS * 32; i += 256) {
        int j = i >> 5;
        float v = 0.0f;
        if (j >= PAD && j < PAD + NW) v = wrow[j - PAD];
        wsh[i] = v;
    }
    __syncthreads();

    const int lane = threadIdx.x & 31;
    const int vec = blockIdx.x * 256 + threadIdx.x;     // float4 index

    float4 xv = ((const float4*)x)[vec];
    float4 ov;

    float xin[4] = {xv.x, xv.y, xv.z, xv.w};
    float oout[4];

#pragma unroll
    for (int e = 0; e < 4; e++) {
        float xx = xin[e];
        float t = fmaf(xx, INVS, INVS);                 // (x + 1) / sigma
        float j0f = rintf(t);
        j0f = fminf(fmaxf(j0f, 0.0f), 62.0f);
        // recompute u from x for accuracy: u = (x - mu_j0) / sigma
        float u = (xx - fmaf(j0f, SIGMA, -1.0f)) * INVS;
        u = fminf(fmaxf(u, -12.0f), 12.0f);             // keep b^6 finite

        float a  = __expf(-0.5f * u * u);
        float b  = __expf(u);
        float bi = __expf(-u);

        int base = (((int)j0f + PAD) << 5) | lane;

        float acc = wsh[base];                          // k = 0, c0 = 1
        float bp = b, bn = bi;
        acc = fmaf(0.60653066f,  fmaf(bp, wsh[base + 32],  bn * wsh[base - 32]),  acc);
        bp *= b; bn *= bi;
        acc = fmaf(0.13533528f,  fmaf(bp, wsh[base + 64],  bn * wsh[base - 64]),  acc);
        bp *= b; bn *= bi;
        acc = fmaf(0.011108997f, fmaf(bp, wsh[base + 96],  bn * wsh[base - 96]),  acc);
        bp *= b; bn *= bi;
        acc = fmaf(3.3546263e-4f, fmaf(bp, wsh[base + 128], bn * wsh[base - 128]), acc);
        bp *= b; bn *= bi;
        acc = fmaf(3.7266532e-6f, fmaf(bp, wsh[base + 160], bn * wsh[base - 160]), acc);
        bp *= b; bn *= bi;
        acc = fmaf(1.5229979e-8f, fmaf(bp, wsh[base + 192], bn * wsh[base - 192]), acc);

        oout[e] = a * acc;
    }

    ov.x = oout[0]; ov.y = oout[1]; ov.z = oout[2]; ov.w = oout[3];
    ((float4*)out)[vec] = ov;
}

extern "C" void kernel_launch(void* const* d_in, const int* in_sizes, int n_in,
                              void* d_out, int out_size)
{
    const float* x = (const float*)d_in[0];
    const float* w = (const float*)d_in[1];
    float* out = (float*)d_out;

    int n = in_sizes[0];                 // 16*64*96*96 = 9,437,184
    int blocks = n / 1024;               // 256 threads * 4 elems; 9216 blocks
    rbf_act_kernel<<<blocks, 256>>>(x, w, out);
}

// round 3
// speedup vs baseline: 1.8381x; 1.8381x over previous
#include <cuda_runtime.h>
#include <cuda_bf16.h>
#include <cstdint>

// TrainableActivation via per-channel cubic-Hermite LUT.
//
// Phase 1 (build_tab): tabulate f_c(x) = sum_j w[c,j] exp(-(x-mu_j)^2/(2s^2))
//   and h*f_c'(x) at NS=1024 samples over [-1.3, 1.3] for each of 64 channels.
//   Outside +/-1.25 the true f is < 1e-18 (edge Gaussian tail) so clamping x
//   into the table range is exact at fp32. Slot i stores (f_i, m_i, f_{i+1},
//   m_{i+1}) so evaluation needs ONE LDS.128.
//   Hermite error ~ h^4 |f''''|/384 ~ 2.5e-6 abs  << 1e-3 threshold.
//
// Phase 2 (rbf_main): ONE block per (batch,channel) slab of 9216 elements
//   (grid = 16*64 = 1024 blocks, single wave on 148 SMs). Block stages its
//   16KB channel table once, then 256 threads x 9 float4 iterations.
//   Per element: clamp, scale, trunc, one LDS.128, ~8 FMA cubic Hermite.

#define NS     1024
#define XLO   -1.3f
#define INVH   393.46153846f     // (NS-1)/2.6
#define TOFF   511.5f            // -XLO*INVH
#define HSTEP  (2.6f / 1023.0f)

#define SLAB_V4 2304             // 9216 elements / 4

__device__ float4 g_tab[64 * NS];   // 1 MB scratch

// ---------------- Phase 1: table build (64*1024 samples) ----------------
__global__ void build_tab(const float* __restrict__ w)
{
    int s = blockIdx.x * 256 + threadIdx.x;
    int c = s >> 10;
    int i = s & (NS - 1);

    float xi = fmaf((float)i, HSTEP, XLO);
    const float* wr = w + c * 63;

    float f = 0.0f, g = 0.0f;
#pragma unroll 7
    for (int j = 0; j < 63; j++) {
        float mu = fmaf((float)j, 1.0f / 31.0f, -1.0f);
        float d  = xi - mu;
        float e  = __expf(-480.5f * d * d);      // 1/(2 sigma^2) = 31^2/2
        float wj = wr[j];
        f = fmaf(wj, e, f);
        g = fmaf(wj * d, e, g);
    }
    float m = -961.0f * HSTEP * g;               // h * f'(xi)

    // slot i gets (f,m) in .xy ; slot i-1 gets same sample in .zw
    float2* t2 = (float2*)g_tab;
    t2[(c << 11) + 2 * i] = make_float2(f, m);
    if (i > 0)
        t2[(c << 11) + 2 * i - 1] = make_float2(f, m);
}

// ---------------- Phase 2: main ----------------
__global__ void __launch_bounds__(256)
rbf_main(const float* __restrict__ x, float* __restrict__ out)
{
    __shared__ float4 tab[NS];      // 16 KB

    const int slab = blockIdx.x;            // batch*64 + chan
    const int chan = slab & 63;

    const float4* gsrc = g_tab + chan * NS;
    for (int i = threadIdx.x; i < NS; i += 256)
        tab[i] = gsrc[i];
    __syncthreads();

    const float4* xs = (const float4*)x + slab * SLAB_V4;
    float4*       os = (float4*)out     + slab * SLAB_V4;

#pragma unroll
    for (int it = 0; it < 9; it++) {
        int v = it * 256 + threadIdx.x;     // 0 .. 2303
        float4 xv = xs[v];

        float xin[4] = {xv.x, xv.y, xv.z, xv.w};
        float res[4];

#pragma unroll
        for (int e = 0; e < 4; e++) {
            float xc = fminf(fmaxf(xin[e], -1.2999f), 1.2999f);
            float t  = fmaf(xc, INVH, TOFF);        // in [0.04, 1022.97]
            int   i  = (int)t;                      // trunc == floor (t >= 0)
            float u  = t - (float)i;

            float4 s = tab[i];                      // f0, m0, f1, m1
            float del = s.z - s.x;
            float sm  = s.y + s.w;
            float c3  = fmaf(-2.0f, del, sm);       // m0+m1-2*del
            float c2  = (del - s.y) - c3;           // 3*del-2*m0-m1
            float p   = fmaf(u, c3, c2);
            p = fmaf(u, p, s.y);
            p = fmaf(u, p, s.x);
            res[e] = p;
        }

        float4 ov = {res[0], res[1], res[2], res[3]};
        os[v] = ov;
    }
}

extern "C" void kernel_launch(void* const* d_in, const int* in_sizes, int n_in,
                              void* d_out, int out_size)
{
    const float* x = (const float*)d_in[0];
    const float* w = (const float*)d_in[1];
    float* out = (float*)d_out;

    build_tab<<<256, 256>>>(w);

    int n = in_sizes[0];                 // 9,437,184
    rbf_main<<<n / 9216, 256>>>(x, out); // 1024 blocks, one slab each
}

// round 4
// speedup vs baseline: 2.0057x; 1.0912x over previous
#include <cuda_runtime.h>
#include <cuda_bf16.h>
#include <cstdint>

// TrainableActivation via per-channel LINEAR LUT (NS=4096 samples/channel).
//
// Phase 1 (build_tab): tabulate f_c(x) at 4096 samples over [-1.3, 1.3] per
//   channel using the 3-exp windowed RBF identity (±6 taps, err < 3e-7):
//     exp(-(u-k)^2/2) = exp(-u^2/2) * exp(u)^k * exp(-k^2/2)
//   Slot i stores (f_i, f_{i+1}) so evaluation needs ONE LDS.64.
//   Linear-interp error: h^2 |f''|/8 <= 2e-4 abs worst-case (norm-rel ~1e-4).
//
// Phase 2 (rbf_main): ONE block per (batch,channel) slab of 9216 elements
//   (grid = 1024). Stage the 32KB channel table, then 256 threads x 9 float4
//   iterations: clamp, scale, trunc, one LDS.64, one lerp.

#define NS      4096
#define XLO    -1.3f
#define INVH    1575.0f          // (NS-1)/2.6 = 4095/2.6 exactly
#define TOFF    2047.5f          // -XLO * INVH
#define HSTEP   (2.6f / 4095.0f)

#define SLAB_V4 2304             // 9216 / 4

__device__ float2 g_tab[64 * NS];   // 2 MB scratch

// ---------------- Phase 1: table build ----------------
// 64 blocks (one per channel) x 256 threads x 16 samples
__global__ void build_tab(const float* __restrict__ w)
{
    __shared__ float wpad[75];          // w row padded +/-6 with zeros
    const int c = blockIdx.x;

    if (threadIdx.x < 75) {
        int j = (int)threadIdx.x - 6;
        wpad[threadIdx.x] = (j >= 0 && j < 63) ? w[c * 63 + j] : 0.0f;
    }
    __syncthreads();

    float2* trow = g_tab + c * NS;

    for (int it = 0; it < 16; it++) {
        int i = it * 256 + threadIdx.x;                 // 0..4095
        float xi = fmaf((float)i, HSTEP, XLO);

        float t = fmaf(xi, 31.0f, 31.0f);               // knot coordinate
        float j0f = rintf(t);
        j0f = fminf(fmaxf(j0f, 0.0f), 62.0f);
        float u = (xi - fmaf(j0f, 1.0f / 31.0f, -1.0f)) * 31.0f;
        u = fminf(fmaxf(u, -12.0f), 12.0f);

        float a  = __expf(-0.5f * u * u);
        float b  = __expf(u);
        float bi = __expf(-u);
        int base = (int)j0f + 6;

        float f = wpad[base];
        float bp = b, bn = bi;
        f = fmaf(0.60653066f,   fmaf(bp, wpad[base + 1], bn * wpad[base - 1]), f);
        bp *= b; bn *= bi;
        f = fmaf(0.13533528f,   fmaf(bp, wpad[base + 2], bn * wpad[base - 2]), f);
        bp *= b; bn *= bi;
        f = fmaf(0.011108997f,  fmaf(bp, wpad[base + 3], bn * wpad[base - 3]), f);
        bp *= b; bn *= bi;
        f = fmaf(3.3546263e-4f, fmaf(bp, wpad[base + 4], bn * wpad[base - 4]), f);
        bp *= b; bn *= bi;
        f = fmaf(3.7266532e-6f, fmaf(bp, wpad[base + 5], bn * wpad[base - 5]), f);
        bp *= b; bn *= bi;
        f = fmaf(1.5229979e-8f, fmaf(bp, wpad[base + 6], bn * wpad[base - 6]), f);
        f *= a;

        // slot i .x = f_i ; slot i-1 .y = f_i  (duplicated-pair layout)
        float* tf = (float*)trow;
        tf[2 * i] = f;
        if (i > 0) tf[2 * i - 1] = f;
    }
}

// ---------------- Phase 2: main ----------------
__global__ void __launch_bounds__(256)
rbf_main(const float* __restrict__ x, float* __restrict__ out)
{
    __shared__ float2 tab[NS];          // 32 KB

    const int slab = blockIdx.x;        // batch*64 + chan
    const int chan = slab & 63;

    const float4* gsrc = (const float4*)(g_tab + chan * NS);
    float4* tdst = (float4*)tab;
    for (int i = threadIdx.x; i < NS / 2; i += 256)
        tdst[i] = gsrc[i];
    __syncthreads();

    const float4* xs = (const float4*)x + slab * SLAB_V4;
    float4*       os = (float4*)out     + slab * SLAB_V4;

#pragma unroll
    for (int it = 0; it < 9; it++) {
        int v = it * 256 + threadIdx.x;             // 0..2303
        float4 xv = xs[v];

        float xin[4] = {xv.x, xv.y, xv.z, xv.w};
        float res[4];

#pragma unroll
        for (int e = 0; e < 4; e++) {
            float xc = fminf(fmaxf(xin[e], -1.2999f), 1.2999f);
            float t  = fmaf(xc, INVH, TOFF);        // in [0.07, 4094.85]
            int   i  = (int)t;                      // trunc == floor (t >= 0)
            float u  = t - (float)i;

            float2 s = tab[i];                      // f_i, f_{i+1}
            res[e] = fmaf(u, s.y - s.x, s.x);
        }

        float4 ov = {res[0], res[1], res[2], res[3]};
        os[v] = ov;
    }
}

extern "C" void kernel_launch(void* const* d_in, const int* in_sizes, int n_in,
                              void* d_out, int out_size)
{
    const float* x = (const float*)d_in[0];
    const float* w = (const float*)d_in[1];
    float* out = (float*)d_out;

    build_tab<<<64, 256>>>(w);

    int n = in_sizes[0];                 // 9,437,184
    rbf_main<<<n / 9216, 256>>>(x, out); // 1024 blocks, one slab each
}

// round 6
// speedup vs baseline: 2.3234x; 1.1584x over previous
#include <cuda_runtime.h>
#include <cuda_bf16.h>
#include <cstdint>

// TrainableActivation via per-channel LINEAR LUT (NS=4096 samples/channel).
//
// Phase 1 (build_tab): tabulate f_c(x) at 4096 samples over [-1.3, 1.3] per
//   channel using the 3-exp windowed RBF identity (±6 taps, err < 3e-7).
//   256 blocks = 4 per channel, 1024 samples each.
//
// Phase 2 (rbf_main): ONE block per (batch,channel) slab of 9216 elements
//   (grid = 1024 = ONE full wave at 8 blocks/SM). Stage the 16KB channel
//   table, then 256 threads x 9 float4 iters: clamp, scale, trunc,
//   two LDS.32, one lerp. __launch_bounds__(256,8) keeps regs <= 32 so
//   2048 threads/SM are resident (no wave tail, max latency cover).
//   x/out use streaming (.cs) hints so the one-shot payload doesn't evict
//   the L2-resident LUT.

#define NS      4096
#define XLO    -1.3f
#define INVH    1575.0f          // (NS-1)/2.6 = 4095/2.6 exactly
#define TOFF    2047.5f          // -XLO * INVH
#define HSTEP   (2.6f / 4095.0f)

#define SLAB_V4 2304             // 9216 / 4

__device__ float g_tabf[64 * NS];   // 1 MB scratch

// ---------------- Phase 1: table build ----------------
// 256 blocks (4 per channel) x 256 threads x 4 samples
__global__ void build_tab(const float* __restrict__ w)
{
    __shared__ float wpad[75];          // w row padded +/-6 with zeros
    const int c    = blockIdx.x >> 2;   // channel
    const int part = blockIdx.x & 3;    // quarter of the row

    if (threadIdx.x < 75) {
        int j = (int)threadIdx.x - 6;
        wpad[threadIdx.x] = (j >= 0 && j < 63) ? w[c * 63 + j] : 0.0f;
    }
    __syncthreads();

    float* trow = g_tabf + c * NS;

#pragma unroll
    for (int it = 0; it < 4; it++) {
        int i = part * 1024 + it * 256 + threadIdx.x;   // 0..4095
        float xi = fmaf((float)i, HSTEP, XLO);

        float t = fmaf(xi, 31.0f, 31.0f);               // knot coordinate
        float j0f = rintf(t);
        j0f = fminf(fmaxf(j0f, 0.0f), 62.0f);
        float u = (xi - fmaf(j0f, 1.0f / 31.0f, -1.0f)) * 31.0f;
        u = fminf(fmaxf(u, -12.0f), 12.0f);

        float a  = __expf(-0.5f * u * u);
        float b  = __expf(u);
        float bi = __expf(-u);
        int base = (int)j0f + 6;

        float f = wpad[base];
        float bp = b, bn = bi;
        f = fmaf(0.60653066f,   fmaf(bp, wpad[base + 1], bn * wpad[base - 1]), f);
        bp *= b; bn *= bi;
        f = fmaf(0.13533528f,   fmaf(bp, wpad[base + 2], bn * wpad[base - 2]), f);
        bp *= b; bn *= bi;
        f = fmaf(0.011108997f,  fmaf(bp, wpad[base + 3], bn * wpad[base - 3]), f);
        bp *= b; bn *= bi;
        f = fmaf(3.3546263e-4f, fmaf(bp, wpad[base + 4], bn * wpad[base - 4]), f);
        bp *= b; bn *= bi;
        f = fmaf(3.7266532e-6f, fmaf(bp, wpad[base + 5], bn * wpad[base - 5]), f);
        bp *= b; bn *= bi;
        f = fmaf(1.5229979e-8f, fmaf(bp, wpad[base + 6], bn * wpad[base - 6]), f);

        trow[i] = a * f;
    }
}

// ---------------- Phase 2: main ----------------
__global__ void __launch_bounds__(256, 8)
rbf_main(const float* __restrict__ x, float* __restrict__ out)
{
    __shared__ float tab[NS];           // 16 KB

    const int slab = blockIdx.x;        // batch*64 + chan
    const int chan = slab & 63;

    const float4* gsrc = (const float4*)(g_tabf + chan * NS);
    float4* tdst = (float4*)tab;
    for (int i = threadIdx.x; i < NS / 4; i += 256)
        tdst[i] = gsrc[i];
    __syncthreads();

    const float4* xs = (const float4*)x + slab * SLAB_V4;
    float4*       os = (float4*)out     + slab * SLAB_V4;

#pragma unroll
    for (int it = 0; it < 9; it++) {
        int v = it * 256 + threadIdx.x;             // 0..2303
        float4 xv = __ldcs(&xs[v]);                 // streaming read (one-shot)

        float xin[4] = {xv.x, xv.y, xv.z, xv.w};
        float res[4];

#pragma unroll
        for (int e = 0; e < 4; e++) {
            float xc = fminf(fmaxf(xin[e], -1.2999f), 1.2999f);
            float t  = fmaf(xc, INVH, TOFF);        // in [0.15, 4094.85]
            int   i  = (int)t;                      // trunc == floor (t >= 0)
            float u  = t - (float)i;

            float f0 = tab[i];
            float f1 = tab[i + 1];
            res[e] = fmaf(u, f1 - f0, f0);
        }

        float4 ov = {res[0], res[1], res[2], res[3]};
        __stcs(&os[v], ov);                         // streaming write (one-shot)
    }
}

extern "C" void kernel_launch(void* const* d_in, const int* in_sizes, int n_in,
                              void* d_out, int out_size)
{
    const float* x = (const float*)d_in[0];
    const float* w = (const float*)d_in[1];
    float* out = (float*)d_out;

    build_tab<<<256, 256>>>(w);

    int n = in_sizes[0];                 // 9,437,184
    rbf_main<<<n / 9216, 256>>>(x, out); // 1024 blocks, one slab each, 1 wave
}